// round 16
// baseline (speedup 1.0000x reference)
#include <cuda_runtime.h>
#include <math.h>

// Problem constants
#define BB 2
#define TT 2048
#define HH 2048
#define NHH 16
#define HDD 128
#define MM (BB*TT)     // 4096 rows
#define FF (4*HH)      // 8192 ffn dim

// ---------------- scratch (static device globals; no allocs) ----------------
__device__ float g_h[(size_t)MM * HH];      // LN output (reused for LN1 and LN2)
__device__ float g_q[(size_t)MM * HH];
__device__ float g_k[(size_t)MM * HH];
__device__ float g_v[(size_t)MM * HH];
__device__ float g_attn[(size_t)MM * HH];
__device__ float g_act[(size_t)MM * FF];    // FFN hidden activations
// tf32-rounded weight copies
__device__ float g_wq[(size_t)HH * HH];
__device__ float g_wk[(size_t)HH * HH];
__device__ float g_wv[(size_t)HH * HH];
__device__ float g_wo[(size_t)HH * HH];
__device__ float g_w1[(size_t)HH * FF];
__device__ float g_w2[(size_t)FF * HH];

__device__ __forceinline__ unsigned f2tf(float x) {
    unsigned u;
    asm("cvt.rna.tf32.f32 %0, %1;" : "=r"(u) : "f"(x));
    return u;
}
__device__ __forceinline__ float roundtf(float x) { return __uint_as_float(f2tf(x)); }

// gelu-tanh via hardware EX2/RCP: tanh(z) = 1 - 2/(1+e^{2z})
// => gelu(x) = x * e^{2z}/(1+e^{2z}), z = 0.79788456(x + 0.044715 x^3).
// Clamp exponent to avoid inf/inf. |err| ~1e-6, far below tf32 noise.
__device__ __forceinline__ float gelu_tanh_f(float x) {
    float z = 0.7978845608028654f * (x + 0.044715f * x * x * x);
    float e = exp2f(fminf(2.8853900817779268f * z, 120.0f));
    return x * __fdividef(e, 1.0f + e);
}

__device__ __forceinline__ void mma_tf32(float d[4], const unsigned a[4], const unsigned b[2]) {
    asm volatile(
        "mma.sync.aligned.m16n8k8.row.col.f32.tf32.tf32.f32 "
        "{%0,%1,%2,%3}, {%4,%5,%6,%7}, {%8,%9}, {%0,%1,%2,%3};\n"
        : "+f"(d[0]), "+f"(d[1]), "+f"(d[2]), "+f"(d[3])
        : "r"(a[0]), "r"(a[1]), "r"(a[2]), "r"(a[3]), "r"(b[0]), "r"(b[1]));
}

__device__ __forceinline__ void cp16(void* smem_dst, const void* gmem_src) {
    unsigned s = (unsigned)__cvta_generic_to_shared(smem_dst);
    asm volatile("cp.async.cg.shared.global [%0], [%1], 16;\n" :: "r"(s), "l"(gmem_src));
}

// ---------------- tf32 pre-rounding of all 6 weight matrices, one launch ----
__global__ void __launch_bounds__(256)
round_all_kernel(const float4* i0, float4* o0, int n0,
                 const float4* i1, float4* o1, int n1,
                 const float4* i2, float4* o2, int n2,
                 const float4* i3, float4* o3, int n3,
                 const float4* i4, float4* o4, int n4,
                 const float4* i5, float4* o5, int n5)
{
    const float4* in; float4* out; int n;
    switch (blockIdx.y) {
        case 0: in = i0; out = o0; n = n0; break;
        case 1: in = i1; out = o1; n = n1; break;
        case 2: in = i2; out = o2; n = n2; break;
        case 3: in = i3; out = o3; n = n3; break;
        case 4: in = i4; out = o4; n = n4; break;
        default: in = i5; out = o5; n = n5; break;
    }
    int i = blockIdx.x * 256 + threadIdx.x;
    if (i < n) {
        float4 v = in[i];
        float4 r;
        r.x = roundtf(v.x); r.y = roundtf(v.y);
        r.z = roundtf(v.z); r.w = roundtf(v.w);
        out[i] = r;
    }
}

// ---------------- LayerNorm: one block per row (tf32-rounded output) --------
__global__ void __launch_bounds__(256)
ln_kernel(const float* __restrict__ x, const float* __restrict__ gam,
          const float* __restrict__ bet, float* __restrict__ y)
{
    const int row = blockIdx.x;
    const int tid = threadIdx.x;
    const float* xr = x + (size_t)row * HH;
    float v[8];
    *(float4*)&v[0] = *(const float4*)(xr + tid * 8);
    *(float4*)&v[4] = *(const float4*)(xr + tid * 8 + 4);
    float s = 0.f, ss = 0.f;
    #pragma unroll
    for (int i = 0; i < 8; i++) { s += v[i]; ss = fmaf(v[i], v[i], ss); }
    #pragma unroll
    for (int off = 16; off > 0; off >>= 1) {
        s  += __shfl_xor_sync(0xffffffffu, s,  off);
        ss += __shfl_xor_sync(0xffffffffu, ss, off);
    }
    __shared__ float rs[8], rss[8], stats[2];
    const int warp = tid >> 5;
    if ((tid & 31) == 0) { rs[warp] = s; rss[warp] = ss; }
    __syncthreads();
    if (tid == 0) {
        float S = 0.f, SS = 0.f;
        #pragma unroll
        for (int w = 0; w < 8; w++) { S += rs[w]; SS += rss[w]; }
        float mean = S * (1.0f / HH);
        float var  = SS * (1.0f / HH) - mean * mean;
        stats[0] = mean;
        stats[1] = rsqrtf(var + 1e-5f);
    }
    __syncthreads();
    const float mean = stats[0], inv = stats[1];
    float g[8], b[8];
    *(float4*)&g[0] = *(const float4*)(gam + tid * 8);
    *(float4*)&g[4] = *(const float4*)(gam + tid * 8 + 4);
    *(float4*)&b[0] = *(const float4*)(bet + tid * 8);
    *(float4*)&b[4] = *(const float4*)(bet + tid * 8 + 4);
    float o[8];
    #pragma unroll
    for (int i = 0; i < 8; i++) o[i] = roundtf(fmaf(g[i], (v[i] - mean) * inv, b[i]));
    float* yp = y + (size_t)row * HH + tid * 8;
    *(float4*)yp       = make_float4(o[0], o[1], o[2], o[3]);
    *(float4*)(yp + 4) = make_float4(o[4], o[5], o[6], o[7]);
}

// ---------------- TF32 GEMM, 4-stage cp.async pipeline (known-good R12) -----
// EPI 0: C = tf32(acc)     EPI 1: C = acc + res
// EPI 2: C = tf32(gelu(acc + bias[n]))   EPI 3: C = acc + bias[n] + C
template<int EPI>
__global__ void __launch_bounds__(256, 2)
gemm_tc(const float* __restrict__ A, const float* __restrict__ B,
        const float* __restrict__ bias, const float* __restrict__ res,
        float* __restrict__ C, int M, int N, int K)
{
    extern __shared__ float smem[];
    float* sA = smem;                 // 4 stages x 128*20
    float* sB = smem + 4 * 2560;      // 4 stages x 16*136

    const int tid  = threadIdx.x;
    const int lane = tid & 31;
    const int warp = tid >> 5;
    const int l4 = lane & 3;
    const int l2 = lane >> 2;
    const int wm = (warp & 3) * 32;
    const int wn = (warp >> 2) * 64;
    const int m0 = blockIdx.y * 128;
    const int n0 = blockIdx.x * 128;

    const int am  = tid >> 2;
    const int akq = (tid & 3) * 4;
    const int bk  = tid >> 5;
    const int bnq = (tid & 31) * 4;

    float acc[2][8][4];
    #pragma unroll
    for (int mi = 0; mi < 2; mi++)
        #pragma unroll
        for (int ni = 0; ni < 8; ni++)
            #pragma unroll
            for (int r = 0; r < 4; r++) acc[mi][ni][r] = 0.f;

    const int nt = K >> 4;

    auto issue = [&](int stage, int kt) {
        const int k0 = kt << 4;
        float* a_s = sA + stage * 2560;
        float* b_s = sB + stage * 2176;
        cp16(a_s + am * 20 + akq,        A + (size_t)(m0 + am) * K + k0 + akq);
        cp16(a_s + (am + 64) * 20 + akq, A + (size_t)(m0 + am + 64) * K + k0 + akq);
        cp16(b_s + bk * 136 + bnq,       B + (size_t)(k0 + bk) * N + n0 + bnq);
        cp16(b_s + (bk + 8) * 136 + bnq, B + (size_t)(k0 + bk + 8) * N + n0 + bnq);
    };

    #pragma unroll
    for (int s = 0; s < 3; s++) {
        issue(s, s);
        asm volatile("cp.async.commit_group;\n");
    }

    for (int it = 0; it < nt; ++it) {
        asm volatile("cp.async.wait_group 2;\n");
        __syncthreads();
        const int pf = it + 3;
        if (pf < nt) issue(pf & 3, pf);
        asm volatile("cp.async.commit_group;\n");

        const float* As_ = sA + (it & 3) * 2560;
        const float* Bs_ = sB + (it & 3) * 2176;
        #pragma unroll
        for (int kb = 0; kb < 16; kb += 8) {
            unsigned af[2][4];
            #pragma unroll
            for (int mi = 0; mi < 2; mi++) {
                const float* ap = As_ + (wm + mi * 16 + l2) * 20 + kb + l4;
                af[mi][0] = __float_as_uint(ap[0]);
                af[mi][1] = __float_as_uint(ap[160]);
                af[mi][2] = __float_as_uint(ap[4]);
                af[mi][3] = __float_as_uint(ap[164]);
            }
            unsigned bf[8][2];
            #pragma unroll
            for (int ni = 0; ni < 8; ni++) {
                const float* bp = Bs_ + (kb + l4) * 136 + wn + ni * 8 + l2;
                bf[ni][0] = __float_as_uint(bp[0]);
                bf[ni][1] = __float_as_uint(bp[544]);
            }
            #pragma unroll
            for (int mi = 0; mi < 2; mi++)
                #pragma unroll
                for (int ni = 0; ni < 8; ni++)
                    mma_tf32(acc[mi][ni], af[mi], bf[ni]);
        }
    }

    #pragma unroll
    for (int mi = 0; mi < 2; mi++) {
        #pragma unroll
        for (int h = 0; h < 2; h++) {
            const int row = m0 + wm + mi * 16 + h * 8 + l2;
            #pragma unroll
            for (int ni = 0; ni < 8; ni++) {
                const int col = n0 + wn + ni * 8 + l4 * 2;
                const size_t off = (size_t)row * N + col;
                float v0 = acc[mi][ni][2 * h];
                float v1 = acc[mi][ni][2 * h + 1];
                if (EPI == 0) {
                    v0 = roundtf(v0); v1 = roundtf(v1);   // QKV feed attn raw cp.async
                } else if (EPI == 1) {
                    float2 r = *(const float2*)(res + off);
                    v0 += r.x; v1 += r.y;
                } else if (EPI == 2) {
                    v0 = roundtf(gelu_tanh_f(v0 + bias[col]));
                    v1 = roundtf(gelu_tanh_f(v1 + bias[col + 1]));
                } else if (EPI == 3) {
                    float2 c = *(const float2*)(C + off);
                    v0 += c.x + bias[col];
                    v1 += c.y + bias[col + 1];
                }
                *(float2*)(C + off) = make_float2(v0, v1);
            }
        }
    }
}

// ---------------- TF32 flash attention, 2-stage cp.async K/V pipeline -------
// CTA: 128 q-rows x one head; 8 warps, warp w owns rows [16w, 16w+16).
// P staging is warp-private -> only __syncwarp between P store and PV.
// Ps stride 68: PV a-frag loads bank-clean. smem = 172032 B.
__global__ void __launch_bounds__(256, 1)
attn_tc(const float* __restrict__ Q, const float* __restrict__ K,
        const float* __restrict__ V, float* __restrict__ Out)
{
    extern __shared__ unsigned smu[];
    unsigned* Ps = smu + 34304;    // [128][68]

    const int tid  = threadIdx.x;
    const int lane = tid & 31;
    const int warp = tid >> 5;
    const int l4 = lane & 3;
    const int l2 = lane >> 2;
    const int wm = warp * 16;
    const int blk = gridDim.x - 1 - blockIdx.x;    // heavy diagonal CTAs first
    const int q0 = blk * 128;
    const int b  = blockIdx.y >> 4;
    const int h  = blockIdx.y & 15;
    const size_t base = (size_t)b * TT * HH + (size_t)h * HDD;
    const float qscale = 0.12751744116f;   // log2(e) / sqrt(128)

    const int nkt = 2 * blk + 2;

    auto issue_kv = [&](int stage, int kt) {
        unsigned* Ks = smu + stage * 17152;
        unsigned* Vs = Ks + 8448;
        const int k0 = kt * 64;
        #pragma unroll
        for (int it = 0; it < 8; it++) {
            int chunk = tid + it * 256;
            int key = chunk >> 5;
            int d0  = (chunk & 31) << 2;
            cp16(&Ks[key * 132 + d0], K + base + (size_t)(k0 + key) * HH + d0);
            cp16(&Vs[key * 136 + d0], V + base + (size_t)(k0 + key) * HH + d0);
        }
    };

    issue_kv(0, 0);
    asm volatile("cp.async.commit_group;\n");

    // Q a-frags: 16 k-steps x 4 regs, resident for the whole CTA
    unsigned qf[16][4];
    {
        const float* Qr0 = Q + base + (size_t)(q0 + wm + l2) * HH;
        const float* Qr1 = Qr0 + 8 * HH;
        #pragma unroll
        for (int ks = 0; ks < 16; ks++) {
            qf[ks][0] = f2tf(Qr0[ks * 8 + l4]     * qscale);
            qf[ks][1] = f2tf(Qr1[ks * 8 + l4]     * qscale);
            qf[ks][2] = f2tf(Qr0[ks * 8 + l4 + 4] * qscale);
            qf[ks][3] = f2tf(Qr1[ks * 8 + l4 + 4] * qscale);
        }
    }

    float o[16][4];
    #pragma unroll
    for (int nf = 0; nf < 16; nf++)
        #pragma unroll
        for (int r = 0; r < 4; r++) o[nf][r] = 0.f;
    float m0r = -1e30f, m1r = -1e30f;
    float l0r = 0.f,    l1r = 0.f;

    for (int kt = 0; kt < nkt; kt++) {
        if (kt + 1 < nkt) {
            issue_kv((kt + 1) & 1, kt + 1);
            asm volatile("cp.async.commit_group;\n");
            asm volatile("cp.async.wait_group 1;\n");
        } else {
            asm volatile("cp.async.wait_group 0;\n");
        }
        __syncthreads();
        const unsigned* Ks = smu + (kt & 1) * 17152;
        const unsigned* Vs = Ks + 8448;
        const int k0 = kt * 64;

        // ---- S = Q @ K^T ----
        float sc[8][4];
        #pragma unroll
        for (int ni = 0; ni < 8; ni++)
            #pragma unroll
            for (int r = 0; r < 4; r++) sc[ni][r] = 0.f;
        #pragma unroll
        for (int ks = 0; ks < 16; ks++) {
            #pragma unroll
            for (int ni = 0; ni < 8; ni++) {
                unsigned bf[2];
                const unsigned* kp = &Ks[(ni * 8 + l2) * 132 + ks * 8 + l4];
                bf[0] = kp[0];
                bf[1] = kp[4];
                mma_tf32(sc[ni], qf[ks], bf);
            }
        }

        // ---- causal mask ----
        if (kt >= 2 * blk) {
            const int row0 = q0 + wm + l2;
            const int row1 = row0 + 8;
            #pragma unroll
            for (int ni = 0; ni < 8; ni++) {
                const int col = k0 + ni * 8 + 2 * l4;
                if (col     > row0) sc[ni][0] = -1e30f;
                if (col + 1 > row0) sc[ni][1] = -1e30f;
                if (col     > row1) sc[ni][2] = -1e30f;
                if (col + 1 > row1) sc[ni][3] = -1e30f;
            }
        }

        // ---- online softmax in fragment registers ----
        float mx0 = -1e30f, mx1 = -1e30f;
        #pragma unroll
        for (int ni = 0; ni < 8; ni++) {
            mx0 = fmaxf(mx0, fmaxf(sc[ni][0], sc[ni][1]));
            mx1 = fmaxf(mx1, fmaxf(sc[ni][2], sc[ni][3]));
        }
        mx0 = fmaxf(mx0, __shfl_xor_sync(0xffffffffu, mx0, 1));
        mx0 = fmaxf(mx0, __shfl_xor_sync(0xffffffffu, mx0, 2));
        mx1 = fmaxf(mx1, __shfl_xor_sync(0xffffffffu, mx1, 1));
        mx1 = fmaxf(mx1, __shfl_xor_sync(0xffffffffu, mx1, 2));
        const float mn0 = fmaxf(m0r, mx0);
        const float mn1 = fmaxf(m1r, mx1);
        float sum0 = 0.f, sum1 = 0.f;
        #pragma unroll
        for (int ni = 0; ni < 8; ni++) {
            sc[ni][0] = exp2f(sc[ni][0] - mn0);
            sc[ni][1] = exp2f(sc[ni][1] - mn0);
            sc[ni][2] = exp2f(sc[ni][2] - mn1);
            sc[ni][3] = exp2f(sc[ni][3] - mn1);
            sum0 += sc[ni][0] + sc[ni][1];
            sum1 += sc[ni][2] + sc[ni][3];
        }
        sum0 += __shfl_xor_sync(0xffffffffu, sum0, 1);
        sum0 += __shfl_xor_sync(0xffffffffu, sum0, 2);
        sum1 += __shfl_xor_sync(0xffffffffu, sum1, 1);
        sum1 += __shfl_xor_sync(0xffffffffu, sum1, 2);
        const float a0 = exp2f(m0r - mn0);
        const float a1 = exp2f(m1r - mn1);
        m0r = mn0; m1r = mn1;
        l0r = fmaf(a0, l0r, sum0);
        l1r = fmaf(a1, l1r, sum1);

        // ---- stage P (tf32), warp-private rows ----
        {
            unsigned* p0 = &Ps[(wm + l2)     * 68 + 2 * l4];
            unsigned* p1 = &Ps[(wm + l2 + 8) * 68 + 2 * l4];
            #pragma unroll
            for (int ni = 0; ni < 8; ni++) {
                uint2 t0; t0.x = f2tf(sc[ni][0]); t0.y = f2tf(sc[ni][1]);
                *(uint2*)&p0[ni * 8] = t0;
                uint2 t1; t1.x = f2tf(sc[ni][2]); t1.y = f2tf(sc[ni][3]);
                *(uint2*)&p1[ni * 8] = t1;
            }
        }
        __syncwarp();   // cross-lane STS->LDS visibility; no CTA barrier needed

        #pragma unroll
        for (int nf = 0; nf < 16; nf++) {
            o[nf][0] *= a0; o[nf][1] *= a0;
            o[nf][2] *= a1; o[nf][3] *= a1;
        }

        // ---- O += P @ V ----
        #pragma unroll
        for (int kv = 0; kv < 8; kv++) {
            unsigned af[4];
            const unsigned* pr0 = &Ps[(wm + l2)     * 68 + kv * 8 + l4];
            const unsigned* pr1 = &Ps[(wm + l2 + 8) * 68 + kv * 8 + l4];
            af[0] = pr0[0];
            af[1] = pr1[0];
            af[2] = pr0[4];
            af[3] = pr1[4];
            #pragma unroll
            for (int nf = 0; nf < 16; nf++) {
                unsigned bf[2];
                const unsigned* vp = &Vs[(kv * 8 + l4) * 136 + nf * 8 + l2];
                bf[0] = vp[0];
                bf[1] = vp[4 * 136];
                mma_tf32(o[nf], af, bf);
            }
        }
        __syncthreads();   // all PV reads done before next prefetch overwrites
    }

    // ---- normalize and write (tf32-rounded: feeds gemm_tc<1> A) ----
    const float inv0 = 1.0f / l0r;
    const float inv1 = 1.0f / l1r;
    float* O0 = Out + base + (size_t)(q0 + wm + l2) * HH;
    float* O1 = O0 + 8 * HH;
    #pragma unroll
    for (int nf = 0; nf < 16; nf++) {
        *(float2*)&O0[nf * 8 + 2 * l4] = make_float2(roundtf(o[nf][0] * inv0), roundtf(o[nf][1] * inv0));
        *(float2*)&O1[nf * 8 + 2 * l4] = make_float2(roundtf(o[nf][2] * inv1), roundtf(o[nf][3] * inv1));
    }
}

// ---------------- host launcher ----------------
extern "C" void kernel_launch(void* const* d_in, const int* in_sizes, int n_in,
                              void* d_out, int out_size)
{
    const float* x    = (const float*)d_in[0];
    const float* wq   = (const float*)d_in[1];
    const float* wk   = (const float*)d_in[2];
    const float* wv   = (const float*)d_in[3];
    const float* wo   = (const float*)d_in[4];
    const float* ln1s = (const float*)d_in[5];
    const float* ln1b = (const float*)d_in[6];
    const float* ln2s = (const float*)d_in[7];
    const float* ln2b = (const float*)d_in[8];
    const float* w1   = (const float*)d_in[9];
    const float* b1   = (const float*)d_in[10];
    const float* w2   = (const float*)d_in[11];
    const float* b2   = (const float*)d_in[12];
    float* out = (float*)d_out;

    float *h, *q, *k, *v, *attn, *act;
    float *cwq, *cwk, *cwv, *cwo, *cw1, *cw2;
    cudaGetSymbolAddress((void**)&h,    g_h);
    cudaGetSymbolAddress((void**)&q,    g_q);
    cudaGetSymbolAddress((void**)&k,    g_k);
    cudaGetSymbolAddress((void**)&v,    g_v);
    cudaGetSymbolAddress((void**)&attn, g_attn);
    cudaGetSymbolAddress((void**)&act,  g_act);
    cudaGetSymbolAddress((void**)&cwq,  g_wq);
    cudaGetSymbolAddress((void**)&cwk,  g_wk);
    cudaGetSymbolAddress((void**)&cwv,  g_wv);
    cudaGetSymbolAddress((void**)&cwo,  g_wo);
    cudaGetSymbolAddress((void**)&cw1,  g_w1);
    cudaGetSymbolAddress((void**)&cw2,  g_w2);

    const int M = MM, H = HH, F = FF;
    const dim3 gH(H / 128, M / 128);
    const int gsm = (4 * 2560 + 4 * 2176) * 4;     // 75776 B
    cudaFuncSetAttribute(gemm_tc<0>, cudaFuncAttributeMaxDynamicSharedMemorySize, gsm);
    cudaFuncSetAttribute(gemm_tc<1>, cudaFuncAttributeMaxDynamicSharedMemorySize, gsm);
    cudaFuncSetAttribute(gemm_tc<2>, cudaFuncAttributeMaxDynamicSharedMemorySize, gsm);
    cudaFuncSetAttribute(gemm_tc<3>, cudaFuncAttributeMaxDynamicSharedMemorySize, gsm);

    // 0. pre-round all weights to tf32 (single launch)
    {
        const int nHH = H * H / 4, nHF = H * F / 4;
        round_all_kernel<<<dim3((nHF + 255) / 256, 6), 256>>>(
            (const float4*)wq, (float4*)cwq, nHH,
            (const float4*)wk, (float4*)cwk, nHH,
            (const float4*)wv, (float4*)cwv, nHH,
            (const float4*)wo, (float4*)cwo, nHH,
            (const float4*)w1, (float4*)cw1, nHF,
            (const float4*)w2, (float4*)cw2, nHF);
    }

    // 1. LN1 (tf32-rounded output)
    ln_kernel<<<M, 256>>>(x, ln1s, ln1b, h);
    // 2-4. QKV projections (separate launches; known-good template kernels)
    gemm_tc<0><<<gH, 256, gsm>>>(h, cwq, nullptr, nullptr, q, M, H, H);
    gemm_tc<0><<<gH, 256, gsm>>>(h, cwk, nullptr, nullptr, k, M, H, H);
    gemm_tc<0><<<gH, 256, gsm>>>(h, cwv, nullptr, nullptr, v, M, H, H);
    // 5. causal flash attention
    const int smsize = (2 * 17152 + 8704) * 4;     // 172032 B
    cudaFuncSetAttribute(attn_tc, cudaFuncAttributeMaxDynamicSharedMemorySize, smsize);
    attn_tc<<<dim3(TT / 128, BB * NHH), 256, smsize>>>(q, k, v, attn);
    // 6. out = x + attn @ wo
    gemm_tc<1><<<gH, 256, gsm>>>(attn, cwo, nullptr, x, out, M, H, H);
    // 7. LN2
    ln_kernel<<<M, 256>>>(out, ln2s, ln2b, h);
    // 8. act = gelu(h @ w1 + b1)
    gemm_tc<2><<<dim3(F / 128, M / 128), 256, gsm>>>(h, cw1, b1, nullptr, act, M, F, H);
    // 9. out += act @ w2 + b2
    gemm_tc<3><<<gH, 256, gsm>>>(act, cw2, b2, nullptr, out, M, H, F);
}